// round 14
// baseline (speedup 1.0000x reference)
#include <cuda_runtime.h>
#include <cuda_bf16.h>
#include <cstdint>

#define BATCH 32
#define SEQ   512
#define DM    1024
#define NSAMP 1000
#define SPAD  1024
#define LDAH  136                        // smem row stride in halves (128 + 8 pad)
#define STG_A (128*LDAH*2)               // 34816
#define STAGE ((128+256)*LDAH*2)         // 104448: A 128 rows + B 256 rows
#define NIT   32                         // 4 nc * 8 kc
#define OFF_BIAS (2*STAGE)               // 208896
#define OFF_SID  (OFF_BIAS + 4096)       // 212992
#define OFF_MM   (OFF_SID  + 4096)       // 217088  float[4][128]
#define OFF_LL   (OFF_MM   + 2048)       // 219136
#define OFF_TRUE (OFF_LL   + 2048)       // 221184  float[128]
#define SMEM_REQ (OFF_TRUE + 512)        // 221696

// ---------------- scratch (device globals; allocation-free rule) ----------------
__device__ __nv_bfloat16 g_Xbf[BATCH*SEQ*DM];
__device__ float g_loss[BATCH*SEQ];

__device__ __forceinline__ float log_q_f(int id){
    float f = (float)id;
    float p = (logf(f + 2.0f) - logf(f + 1.0f)) / 10.819798284210285f; // log(50001)
    float t = 1000.0f * log1pf(-p);
    return logf(-expm1f(t));
}

// ---------------- fused kernel: prologue prep + mma.sync GEMM + online logsumexp ----------------
// grid 128 (4 CTAs/batch, M=128), 256 threads, 8 warps in 2(M)x4(N) grid of 64x64 tiles.
// A: own rows converted to bf16 in prologue (g_Xbf), streamed via cp.async.
// B: W rows gathered + converted in-flight (LDG f32 -> cvt -> STS), double buffered.
__global__ __launch_bounds__(256,1)
void k_main(const float* __restrict__ X, const int* __restrict__ nexts,
            const int* __restrict__ samp, const float* __restrict__ W,
            const float* __restrict__ bias){
    extern __shared__ char smraw[];
    char* p = smraw;
    const uint32_t sbase = (uint32_t)__cvta_generic_to_shared(p);
    float* sBias = (float*)(p + OFF_BIAS);
    int*   sSid  = (int*)  (p + OFF_SID);
    float* sMM   = (float*)(p + OFF_MM);
    float* sLL   = (float*)(p + OFF_LL);
    float* sTrue = (float*)(p + OFF_TRUE);

    int tid = threadIdx.x, warp = tid >> 5, lane = tid & 31;
    int b = blockIdx.x >> 2, row0 = (blockIdx.x & 3) << 7;
    int m0 = (warp >> 2) * 64, n0 = (warp & 3) * 64;

    // ---- prologue: sampled ids, bias-logq ----
    for (int s = tid; s < SPAD; s += 256){
        int id = (s < NSAMP) ? samp[b*NSAMP + s] : -1;
        sSid[s] = id;
        sBias[s] = (id >= 0) ? (bias[id] - log_q_f(id)) : -1.0e30f;
    }
    // ---- prologue: A f32->bf16 conversion + exact f32 true logits (warp w: rows w*16..+15) ----
    for (int rr = 0; rr < 16; rr++){
        int row  = warp*16 + rr;
        int grow = b*SEQ + row0 + row;
        int id   = nexts[grow];
        const float4* xr = (const float4*)(X + (size_t)grow*DM);
        const float4* wr = (const float4*)(W + (size_t)id*DM);
        uint2* xo = (uint2*)(g_Xbf + (size_t)grow*DM);
        float acc = 0.f;
        #pragma unroll
        for (int j=0;j<8;j++){
            float4 a = xr[lane + j*32], w4 = wr[lane + j*32];
            acc += a.x*w4.x + a.y*w4.y + a.z*w4.z + a.w*w4.w;
            __nv_bfloat162 p0 = __floats2bfloat162_rn(a.x, a.y);
            __nv_bfloat162 p1 = __floats2bfloat162_rn(a.z, a.w);
            uint2 u; u.x = *(uint32_t*)&p0; u.y = *(uint32_t*)&p1;
            xo[lane + j*32] = u;
        }
        #pragma unroll
        for (int off=16; off>0; off>>=1) acc += __shfl_xor_sync(0xffffffffu, acc, off);
        if (lane == 0) sTrue[row] = acc + bias[id] - log_q_f(id);
    }
    __syncthreads();   // sSid/sBias/sTrue + g_Xbf visible to whole CTA

    const __nv_bfloat16* Ag = g_Xbf + (size_t)(b*SEQ + row0)*DM;

    int tv[8];
    #pragma unroll
    for (int mi=0;mi<4;mi++)
    #pragma unroll
    for (int h=0;h<2;h++)
        tv[mi*2+h] = nexts[b*SEQ + row0 + m0 + mi*16 + h*8 + (lane>>2)];
    float m[8], l[8];
    #pragma unroll
    for (int i=0;i<8;i++){ m[i] = -3.0e38f; l[i] = 0.f; }

    // A cp.async coordinates: row base tid>>4, 16B col tid&15, 8 chunks
    int rb = tid >> 4, c8 = tid & 15;
    auto issue_A = [&](int it){
        if (it < NIT){
            int kc = it & 7;
            uint32_t st = sbase + (uint32_t)(it & 1)*STAGE;
            uint32_t d0 = st + (uint32_t)(rb*(LDAH*2) + c8*16);
            const __nv_bfloat16* gA = Ag + (size_t)rb*DM + kc*128 + c8*8;
            #pragma unroll
            for (int i=0;i<8;i++)
                asm volatile("cp.async.cg.shared.global [%0],[%1],16;"
                    :: "r"(d0 + (uint32_t)(i*16*(LDAH*2))), "l"(gA + (size_t)(i*16)*DM));
        }
        asm volatile("cp.async.commit_group;");
    };

    // B loaders: thread == B row (0..255), wave w covers 32 f32 cols
    auto loadB = [&](float4 (&v)[8], int it, int w){
        int nc = it >> 3, kc = it & 7;
        int id = sSid[nc*256 + tid];
        if (id >= 0){
            const float4* src = (const float4*)(W + (size_t)id*DM + kc*128 + w*32);
            #pragma unroll
            for (int j=0;j<8;j++) v[j] = src[j];
        } else {
            #pragma unroll
            for (int j=0;j<8;j++) v[j] = make_float4(0.f,0.f,0.f,0.f);
        }
    };
    auto storeB = [&](float4 (&v)[8], int it, int w){
        char* stB = p + (it & 1)*STAGE + STG_A;
        uint32_t* dst = (uint32_t*)(stB + tid*(LDAH*2) + w*64);
        #pragma unroll
        for (int j=0;j<8;j++){
            __nv_bfloat162 p0 = __floats2bfloat162_rn(v[j].x, v[j].y);
            __nv_bfloat162 p1 = __floats2bfloat162_rn(v[j].z, v[j].w);
            dst[j*2]   = *(uint32_t*)&p0;
            dst[j*2+1] = *(uint32_t*)&p1;
        }
    };

    float acc[4][4+4][4];   // [mi][j][k] — j<8
    auto mma_kk = [&](const __nv_bfloat16* A, const __nv_bfloat16* B, int kk){
        uint32_t af[4][4];
        #pragma unroll
        for (int mi=0;mi<4;mi++){
            const __nv_bfloat16* q = A + (m0 + mi*16 + (lane & 15))*LDAH + kk*16 + (lane >> 4)*8;
            uint32_t sa = (uint32_t)__cvta_generic_to_shared(q);
            asm volatile("ldmatrix.sync.aligned.m8n8.x4.shared.b16 {%0,%1,%2,%3},[%4];"
                : "=r"(af[mi][0]), "=r"(af[mi][1]), "=r"(af[mi][2]), "=r"(af[mi][3]) : "r"(sa));
        }
        uint32_t bfr[8][2];
        #pragma unroll
        for (int j=0;j<8;j+=2){
            const __nv_bfloat16* q = B + (n0 + j*8 + (lane & 7) + (lane >> 4)*8)*LDAH
                                       + kk*16 + ((lane >> 3) & 1)*8;
            uint32_t sb = (uint32_t)__cvta_generic_to_shared(q);
            asm volatile("ldmatrix.sync.aligned.m8n8.x4.shared.b16 {%0,%1,%2,%3},[%4];"
                : "=r"(bfr[j][0]), "=r"(bfr[j][1]), "=r"(bfr[j+1][0]), "=r"(bfr[j+1][1]) : "r"(sb));
        }
        #pragma unroll
        for (int mi=0;mi<4;mi++)
        #pragma unroll
        for (int j=0;j<8;j++){
            asm volatile("mma.sync.aligned.m16n8k16.row.col.f32.bf16.bf16.f32 "
                "{%0,%1,%2,%3},{%4,%5,%6,%7},{%8,%9},{%0,%1,%2,%3};"
                : "+f"(acc[mi][j][0]), "+f"(acc[mi][j][1]), "+f"(acc[mi][j][2]), "+f"(acc[mi][j][3])
                : "r"(af[mi][0]), "r"(af[mi][1]), "r"(af[mi][2]), "r"(af[mi][3]),
                  "r"(bfr[j][0]), "r"(bfr[j][1]));
        }
    };

    // ---- fill stage 0 ----
    issue_A(0);
    {
        float4 v[8];
        #pragma unroll
        for (int w=0; w<4; w++){ loadB(v, 0, w); storeB(v, 0, w); }
    }
    asm volatile("cp.async.wait_group 0;");
    __syncthreads();

    // ---- mainloop ----
    for (int it=0; it<NIT; ++it){
        int nc = it >> 3, kc = it & 7;
        int nxt = it + 1;
        bool ld = (nxt < NIT);
        issue_A(nxt);

        if (kc == 0){
            #pragma unroll
            for (int mi=0;mi<4;mi++)
            #pragma unroll
            for (int j=0;j<8;j++)
            #pragma unroll
            for (int k=0;k<4;k++) acc[mi][j][k] = 0.f;
        }

        char* st = p + (it & 1)*STAGE;
        const __nv_bfloat16* A = (const __nv_bfloat16*)st;
        const __nv_bfloat16* B = (const __nv_bfloat16*)(st + STG_A);

        float4 v[8];
        if (ld) loadB(v, nxt, 0);
        mma_kk(A, B, 0); mma_kk(A, B, 1);
        if (ld){ storeB(v, nxt, 0); loadB(v, nxt, 1); }
        mma_kk(A, B, 2); mma_kk(A, B, 3);
        if (ld){ storeB(v, nxt, 1); loadB(v, nxt, 2); }
        mma_kk(A, B, 4); mma_kk(A, B, 5);
        if (ld){ storeB(v, nxt, 2); loadB(v, nxt, 3); }
        mma_kk(A, B, 6); mma_kk(A, B, 7);
        if (ld) storeB(v, nxt, 3);

        if (kc == 7){
            int cb = nc*256 + n0 + (lane & 3)*2;
            float2 bi[8]; int2 si[8];
            #pragma unroll
            for (int j=0;j<8;j++){
                bi[j] = *(const float2*)&sBias[cb + j*8];
                si[j] = *(const int2*)  &sSid [cb + j*8];
            }
            #pragma unroll
            for (int mi=0;mi<4;mi++)
            #pragma unroll
            for (int h=0;h<2;h++){
                int ri = mi*2 + h;
                float bm = -3.0e38f;
                #pragma unroll
                for (int j=0;j<8;j++){
                    float v0 = acc[mi][j][2*h]   + bi[j].x; if (si[j].x == tv[ri]) v0 = -1.0e9f;
                    float v1 = acc[mi][j][2*h+1] + bi[j].y; if (si[j].y == tv[ri]) v1 = -1.0e9f;
                    acc[mi][j][2*h] = v0; acc[mi][j][2*h+1] = v1;
                    bm = fmaxf(bm, fmaxf(v0, v1));
                }
                float nm = fmaxf(m[ri], bm);
                float s = l[ri] * __expf(m[ri] - nm);
                #pragma unroll
                for (int j=0;j<8;j++)
                    s += __expf(acc[mi][j][2*h] - nm) + __expf(acc[mi][j][2*h+1] - nm);
                l[ri] = s; m[ri] = nm;
            }
        }

        asm volatile("cp.async.wait_group 0;");
        __syncthreads();
    }

    // ---- quad merge (lanes share rows across cols) ----
    #pragma unroll
    for (int o=1; o<=2; o<<=1){
        #pragma unroll
        for (int i=0;i<8;i++){
            float om = __shfl_xor_sync(0xffffffffu, m[i], o);
            float ol = __shfl_xor_sync(0xffffffffu, l[i], o);
            float nm = fmaxf(m[i], om);
            l[i] = l[i]*__expf(m[i]-nm) + ol*__expf(om-nm);
            m[i] = nm;
        }
    }
    if ((lane & 3) == 0){
        #pragma unroll
        for (int mi=0;mi<4;mi++)
        #pragma unroll
        for (int h=0;h<2;h++){
            int row = m0 + mi*16 + h*8 + (lane>>2);
            sMM[(warp & 3)*128 + row] = m[mi*2+h];
            sLL[(warp & 3)*128 + row] = l[mi*2+h];
        }
    }
    __syncthreads();
    if (tid < 128){
        float M0 = sMM[tid],     L0 = sLL[tid];
        float M1 = sMM[128+tid], L1 = sLL[128+tid];
        float M2 = sMM[256+tid], L2 = sLL[256+tid];
        float M3 = sMM[384+tid], L3 = sLL[384+tid];
        float nm = fmaxf(fmaxf(M0,M1), fmaxf(M2,M3));
        float L  = L0*__expf(M0-nm) + L1*__expf(M1-nm) + L2*__expf(M2-nm) + L3*__expf(M3-nm);
        float ta = sTrue[tid];
        float fm = fmaxf(nm, ta);
        float FL = L*__expf(nm-fm) + __expf(ta-fm);
        g_loss[b*SEQ + row0 + tid] = logf(FL) + fm - ta;
    }
}

// ---------------- mean ----------------
__global__ void k_final(float* out){
    __shared__ float ss[256];
    float s = 0.f;
    for (int i=threadIdx.x; i<BATCH*SEQ; i+=256) s += g_loss[i];
    ss[threadIdx.x] = s; __syncthreads();
    for (int o=128; o>0; o>>=1){
        if (threadIdx.x < o) ss[threadIdx.x] += ss[threadIdx.x + o];
        __syncthreads();
    }
    if (threadIdx.x == 0) out[0] = 0.5f * ss[0] / (float)(BATCH*SEQ);
}

extern "C" void kernel_launch(void* const* d_in, const int* in_sizes, int n_in,
                              void* d_out, int out_size){
    const float* X     = (const float*)d_in[0];
    const int*   nexts = (const int*)  d_in[1];
    const int*   samp  = (const int*)  d_in[2];
    const float* W     = (const float*)d_in[3];
    const float* bias  = (const float*)d_in[4];
    float* out = (float*)d_out;

    cudaFuncSetAttribute(k_main, cudaFuncAttributeMaxDynamicSharedMemorySize, SMEM_REQ);

    k_main <<<BATCH*4, 256, SMEM_REQ>>>(X, nexts, samp, W, bias);
    k_final<<<1, 256>>>(out);
}